// round 9
// baseline (speedup 1.0000x reference)
#include <cuda_runtime.h>
#include <cuda_bf16.h>
#include <cstdint>

#define MARGIN 9.0f
#define NB  32
#define NEI 100000
#define ND  64
#define TPB 256
#define EPB 128
#define LDR 72        // padded row length in bf16 (144 B): conflict-free ldmatrix/STS

// smem byte offsets
#define SMEM_QH 0                      // qh [32][72] bf16
#define SMEM_QL (SMEM_QH + 32*LDR*2)   // ql [32][72]
#define SMEM_EH (SMEM_QL + 32*LDR*2)   // eh [128][72]
#define SMEM_EL (SMEM_EH + 128*LDR*2)  // el [128][72]
#define SMEM_EN (SMEM_EL + 128*LDR*2)  // enorm [128] f32
#define SMEM_QN (SMEM_EN + 128*4)      // qn [32] f32
#define SMEM_FLAG (SMEM_QN + 32*4)     // is64 flag
#define SMEM_BYTES (SMEM_FLAG + 16)

extern __shared__ __align__(16) unsigned char smem_raw[];

__device__ __forceinline__ void ldsm_x4(uint32_t& r0, uint32_t& r1, uint32_t& r2, uint32_t& r3,
                                        uint32_t addr) {
    asm volatile("ldmatrix.sync.aligned.m8n8.x4.shared.b16 {%0,%1,%2,%3}, [%4];"
                 : "=r"(r0), "=r"(r1), "=r"(r2), "=r"(r3) : "r"(addr));
}
__device__ __forceinline__ void mma_bf16(float* c, const uint32_t* a, uint32_t b0, uint32_t b1) {
    asm volatile("mma.sync.aligned.m16n8k16.row.col.f32.bf16.bf16.f32 "
                 "{%0,%1,%2,%3}, {%4,%5,%6,%7}, {%8,%9}, {%0,%1,%2,%3};"
                 : "+f"(c[0]), "+f"(c[1]), "+f"(c[2]), "+f"(c[3])
                 : "r"(a[0]), "r"(a[1]), "r"(a[2]), "r"(a[3]), "r"(b0), "r"(b1));
}
// packed split of (v0,v1) into bf16x2 hi + bf16x2 lo (v0 in low half):
// 1 cvt + 2 bit-ops + 2 subs + 1 cvt = 3 instr/value
__device__ __forceinline__ void split_pair(float v0, float v1, uint32_t& hp, uint32_t& lp) {
    asm("cvt.rn.bf16x2.f32 %0, %1, %2;" : "=r"(hp) : "f"(v1), "f"(v0));
    uint32_t hf0u = hp << 16;
    uint32_t hf1u = hp & 0xFFFF0000u;
    float l0 = v0 - __uint_as_float(hf0u);
    float l1 = v1 - __uint_as_float(hf1u);
    asm("cvt.rn.bf16x2.f32 %0, %1, %2;" : "=r"(lp) : "f"(l1), "f"(l0));
}

__global__ void __launch_bounds__(TPB, 4) transe_kernel(
    const void* __restrict__ subp, const void* __restrict__ relp,
    const float* __restrict__ emb_e, const float* __restrict__ emb_rel,
    float* __restrict__ out)
{
    const int tid = threadIdx.x;
    const long long ebase = (long long)blockIdx.x * EPB;
    float* enorm = (float*)(smem_raw + SMEM_EN);
    float* qn    = (float*)(smem_raw + SMEM_QN);
    int*   flag  = (int*)(smem_raw + SMEM_FLAG);

    // ---- phase 0: index dtype detection once (jnp.int64 may silently be int32) ----
    if (tid == 0) {
        bool is64 = true;
        const long long* s64 = (const long long*)subp;   // 64B read safe for both layouts
        #pragma unroll
        for (int i = 0; i < 8; i++) {
            long long v = s64[i];
            if (v < 0 || v >= NEI) is64 = false;
        }
        *flag = is64 ? 1 : 0;
    }

    // ---- phase 1: entity fill, all 256 threads, half-row each ----
    {
        int row  = tid >> 1;
        int half = tid & 1;                 // dims [half*32, half*32+32)
        long long ge = ebase + row;
        const float4* src = (const float4*)emb_e;
        float part = 0.f;
        #pragma unroll
        for (int i = 0; i < 4; i++) {       // 8 values per iter
            float4 v0 = make_float4(0.f,0.f,0.f,0.f), v1 = v0;
            if (ge < NEI) {
                v0 = src[ge*16 + half*8 + 2*i];
                v1 = src[ge*16 + half*8 + 2*i + 1];
            }
            uint32_t hp[4], lp[4];
            split_pair(v0.x, v0.y, hp[0], lp[0]);
            split_pair(v0.z, v0.w, hp[1], lp[1]);
            split_pair(v1.x, v1.y, hp[2], lp[2]);
            split_pair(v1.z, v1.w, hp[3], lp[3]);
            part = fmaf(v0.x, v0.x, fmaf(v0.y, v0.y, part));
            part = fmaf(v0.z, v0.z, fmaf(v0.w, v0.w, part));
            part = fmaf(v1.x, v1.x, fmaf(v1.y, v1.y, part));
            part = fmaf(v1.z, v1.z, fmaf(v1.w, v1.w, part));
            int off = (row*LDR + half*32 + 8*i) * 2;
            *(uint4*)(smem_raw + SMEM_EH + off) = make_uint4(hp[0],hp[1],hp[2],hp[3]);
            *(uint4*)(smem_raw + SMEM_EL + off) = make_uint4(lp[0],lp[1],lp[2],lp[3]);
        }
        part += __shfl_xor_sync(0xffffffffu, part, 1);
        if (!half) enorm[row] = part;
    }
    __syncthreads();   // flag ready (and entity smem, though unused until after next bar)

    // ---- phase 2: q fill, all 256 threads: row = tid>>3, 8-dim chunk = tid&7 ----
    {
        bool is64 = (*flag != 0);
        int row = tid >> 3;
        int ch  = tid & 7;                  // dims [ch*8, ch*8+8)
        long long s = is64 ? ((const long long*)subp)[row] : (long long)((const int*)subp)[row];
        long long r = is64 ? ((const long long*)relp)[row] : (long long)((const int*)relp)[row];
        float4 e0 = ((const float4*)emb_e)[s*16 + 2*ch];
        float4 e1 = ((const float4*)emb_e)[s*16 + 2*ch + 1];
        float4 r0 = ((const float4*)emb_rel)[r*16 + 2*ch];
        float4 r1 = ((const float4*)emb_rel)[r*16 + 2*ch + 1];
        float vv[8] = {e0.x+r0.x, e0.y+r0.y, e0.z+r0.z, e0.w+r0.w,
                       e1.x+r1.x, e1.y+r1.y, e1.z+r1.z, e1.w+r1.w};
        uint32_t hp[4], lp[4];
        float part = 0.f;
        #pragma unroll
        for (int j = 0; j < 4; j++) {
            split_pair(vv[2*j], vv[2*j+1], hp[j], lp[j]);
            part = fmaf(vv[2*j], vv[2*j], fmaf(vv[2*j+1], vv[2*j+1], part));
        }
        int off = (row*LDR + ch*8) * 2;
        *(uint4*)(smem_raw + SMEM_QH + off) = make_uint4(hp[0],hp[1],hp[2],hp[3]);
        *(uint4*)(smem_raw + SMEM_QL + off) = make_uint4(lp[0],lp[1],lp[2],lp[3]);
        part += __shfl_xor_sync(0xffffffffu, part, 1);
        part += __shfl_xor_sync(0xffffffffu, part, 2);
        part += __shfl_xor_sync(0xffffffffu, part, 4);
        if (ch == 0) qn[row] = part;
    }
    __syncthreads();

    // ================= tensor-core main (fragment mapping validated in R8) =================
    const int wid = tid >> 5;
    const int ln  = tid & 31;
    const int nbase = wid * 16;          // warp's 16-entity strip

    uint32_t smem_u = (uint32_t)__cvta_generic_to_shared(smem_raw);
    const int arow  = ln & 15;
    const int akoff = (ln >> 4) * 8;
    const int brow  = (ln & 7) + ((ln >> 1) & 8);
    const int bkoff = (ln & 8);
    uint32_t aH = smem_u + SMEM_QH + (arow*LDR + akoff)*2;
    uint32_t aL = smem_u + SMEM_QL + (arow*LDR + akoff)*2;
    uint32_t bH = smem_u + SMEM_EH + ((nbase + brow)*LDR + bkoff)*2;
    uint32_t bL = smem_u + SMEM_EL + ((nbase + brow)*LDR + bkoff)*2;

    // C init: c = -0.5*(qn+en); result dist^2 = -2*c_final
    const int r0 = ln >> 2;
    const int cb = 2 * (ln & 3);
    float c[2][2][4];
    {
        float qv[4] = { qn[r0], qn[r0+8], qn[16+r0], qn[24+r0] };
        #pragma unroll
        for (int nj = 0; nj < 2; nj++) {
            float en0 = enorm[nbase + nj*8 + cb];
            float en1 = enorm[nbase + nj*8 + cb + 1];
            #pragma unroll
            for (int mi = 0; mi < 2; mi++) {
                c[mi][nj][0] = -0.5f*(qv[2*mi]   + en0);
                c[mi][nj][1] = -0.5f*(qv[2*mi]   + en1);
                c[mi][nj][2] = -0.5f*(qv[2*mi+1] + en0);
                c[mi][nj][3] = -0.5f*(qv[2*mi+1] + en1);
            }
        }
    }

    // per kk: B frags once, then A m-halves sequentially (limits live frag regs)
    #pragma unroll
    for (int kk = 0; kk < 4; kk++) {
        const uint32_t ko = kk * 32;
        uint32_t bh[4], bl[4];
        ldsm_x4(bh[0],bh[1],bh[2],bh[3], bH + ko);
        ldsm_x4(bl[0],bl[1],bl[2],bl[3], bL + ko);
        #pragma unroll
        for (int mi = 0; mi < 2; mi++) {
            uint32_t ah[4], al[4];
            ldsm_x4(ah[0],ah[1],ah[2],ah[3], aH + mi*16*LDR*2 + ko);
            ldsm_x4(al[0],al[1],al[2],al[3], aL + mi*16*LDR*2 + ko);
            // dot = Ah*Bh + Ah*Bl + Al*Bh   (lo*lo dropped, ~2^-16)
            mma_bf16(c[mi][0], ah, bh[0], bh[1]);
            mma_bf16(c[mi][1], ah, bh[2], bh[3]);
            mma_bf16(c[mi][0], ah, bl[0], bl[1]);
            mma_bf16(c[mi][1], ah, bl[2], bl[3]);
            mma_bf16(c[mi][0], al, bh[0], bh[1]);
            mma_bf16(c[mi][1], al, bh[2], bh[3]);
        }
    }

    // ---- epilogue: out = MARGIN - sqrt(max(-2c, 0)) ; float2 stores, guarded ----
    #pragma unroll
    for (int mi = 0; mi < 2; mi++) {
        #pragma unroll
        for (int nj = 0; nj < 2; nj++) {
            long long eg = ebase + nbase + nj*8 + cb;
            if (eg < NEI) {   // eg even, NEI even -> pair-safe
                int row = mi*16 + r0;
                float v0 = MARGIN - sqrtf(fmaxf(-2.f * c[mi][nj][0], 0.f));
                float v1 = MARGIN - sqrtf(fmaxf(-2.f * c[mi][nj][1], 0.f));
                float v2 = MARGIN - sqrtf(fmaxf(-2.f * c[mi][nj][2], 0.f));
                float v3 = MARGIN - sqrtf(fmaxf(-2.f * c[mi][nj][3], 0.f));
                *(float2*)(out + (long long)row * NEI + eg)       = make_float2(v0, v1);
                *(float2*)(out + (long long)(row + 8) * NEI + eg) = make_float2(v2, v3);
            }
        }
    }
}

extern "C" void kernel_launch(void* const* d_in, const int* in_sizes, int n_in,
                              void* d_out, int out_size) {
    (void)in_sizes; (void)n_in; (void)out_size;
    const void* sub      = d_in[0];
    const void* rel      = d_in[1];
    const float* emb_e   = (const float*)d_in[2];
    const float* emb_rel = (const float*)d_in[3];
    float* out = (float*)d_out;

    static bool attr_set = false;   // idempotent attribute set (not a memory alloc)
    if (!attr_set) {
        cudaFuncSetAttribute(transe_kernel,
                             cudaFuncAttributeMaxDynamicSharedMemorySize, SMEM_BYTES);
        attr_set = true;
    }

    int grid = (NEI + EPB - 1) / EPB;   // 782 blocks
    transe_kernel<<<grid, TPB, SMEM_BYTES>>>(sub, rel, emb_e, emb_rel, out);
}

// round 10
// speedup vs baseline: 1.2937x; 1.2937x over previous
#include <cuda_runtime.h>
#include <cuda_bf16.h>
#include <cstdint>

#define MARGIN 9.0f
#define NB  32
#define NEI 100000
#define ND  64
#define TPB 256
#define EPB 128
#define LDR 72        // padded q row length in bf16 (144 B): conflict-free ldmatrix/STS

// static smem: QH [32][72] bf16, QL [32][72] bf16, qn [32] f32  = 9344 B
#define SMEM_QH 0
#define SMEM_QL (32*LDR*2)
#define SMEM_QN (2*32*LDR*2)
__shared__ __align__(16) unsigned char smem_s[2*32*LDR*2 + 32*4];

__device__ __forceinline__ void ldsm_x4(uint32_t& r0, uint32_t& r1, uint32_t& r2, uint32_t& r3,
                                        uint32_t addr) {
    asm volatile("ldmatrix.sync.aligned.m8n8.x4.shared.b16 {%0,%1,%2,%3}, [%4];"
                 : "=r"(r0), "=r"(r1), "=r"(r2), "=r"(r3) : "r"(addr));
}
__device__ __forceinline__ void mma_bf16(float* c, const uint32_t* a, uint32_t b0, uint32_t b1) {
    asm volatile("mma.sync.aligned.m16n8k16.row.col.f32.bf16.bf16.f32 "
                 "{%0,%1,%2,%3}, {%4,%5,%6,%7}, {%8,%9}, {%0,%1,%2,%3};"
                 : "+f"(c[0]), "+f"(c[1]), "+f"(c[2]), "+f"(c[3])
                 : "r"(a[0]), "r"(a[1]), "r"(a[2]), "r"(a[3]), "r"(b0), "r"(b1));
}
// packed split of (v0,v1) into bf16x2 hi + bf16x2 lo (v0 in low half)
__device__ __forceinline__ void split_pair(float v0, float v1, uint32_t& hp, uint32_t& lp) {
    asm("cvt.rn.bf16x2.f32 %0, %1, %2;" : "=r"(hp) : "f"(v1), "f"(v0));
    uint32_t hf0u = hp << 16;
    uint32_t hf1u = hp & 0xFFFF0000u;
    float l0 = v0 - __uint_as_float(hf0u);
    float l1 = v1 - __uint_as_float(hf1u);
    asm("cvt.rn.bf16x2.f32 %0, %1, %2;" : "=r"(lp) : "f"(l1), "f"(l0));
}

__global__ void __launch_bounds__(TPB, 3) transe_kernel(
    const void* __restrict__ subp, const void* __restrict__ relp,
    const float* __restrict__ emb_e, const float* __restrict__ emb_rel,
    float* __restrict__ out)
{
    const int tid = threadIdx.x;
    const long long ebase = (long long)blockIdx.x * EPB;
    float* qn = (float*)(smem_s + SMEM_QN);

    const int wid = tid >> 5;
    const int ln  = tid & 31;
    const int nbase = wid * 16;          // warp's 16-entity strip
    const int t = ln & 3;                // k-pair selector within fragment
    const int g = ln >> 2;               // n-row within n8 tile

    // ---- B prefetch (kk=0,1) issued FIRST: independent of q, hides DRAM latency
    // under the q gather chain + barrier. Rows clamped (last block): clamped
    // columns are never stored by the guarded epilogue.
    long long n0 = ebase + nbase + g;
    long long n1 = n0 + 8;
    if (n0 > NEI - 1) n0 = NEI - 1;
    if (n1 > NEI - 1) n1 = NEI - 1;
    const float* pB0 = emb_e + n0 * ND + 2 * t;
    const float* pB1 = emb_e + n1 * ND + 2 * t;
    float2 buf[2][4];
    #pragma unroll
    for (int kk = 0; kk < 2; kk++) {
        buf[kk][0] = *(const float2*)(pB0 + kk*16);
        buf[kk][1] = *(const float2*)(pB0 + kk*16 + 8);
        buf[kk][2] = *(const float2*)(pB1 + kk*16);
        buf[kk][3] = *(const float2*)(pB1 + kk*16 + 8);
    }

    // ---- q fill: row = tid>>3, 8-dim chunk = tid&7; hi/lo bf16 to smem ----
    {
        // index dtype detection (jnp.int64 may silently be int32); 64B read safe.
        bool is64 = true;
        const long long* s64 = (const long long*)subp;
        #pragma unroll
        for (int i = 0; i < 8; i++) {
            long long v = s64[i];
            if (v < 0 || v >= NEI) is64 = false;
        }
        int row = tid >> 3;
        int ch  = tid & 7;                  // dims [ch*8, ch*8+8)
        long long s = is64 ? ((const long long*)subp)[row] : (long long)((const int*)subp)[row];
        long long r = is64 ? ((const long long*)relp)[row] : (long long)((const int*)relp)[row];
        float4 e0 = ((const float4*)emb_e)[s*16 + 2*ch];
        float4 e1 = ((const float4*)emb_e)[s*16 + 2*ch + 1];
        float4 r0v = ((const float4*)emb_rel)[r*16 + 2*ch];
        float4 r1v = ((const float4*)emb_rel)[r*16 + 2*ch + 1];
        float vv[8] = {e0.x+r0v.x, e0.y+r0v.y, e0.z+r0v.z, e0.w+r0v.w,
                       e1.x+r1v.x, e1.y+r1v.y, e1.z+r1v.z, e1.w+r1v.w};
        uint32_t hp[4], lp[4];
        float part = 0.f;
        #pragma unroll
        for (int j = 0; j < 4; j++) {
            split_pair(vv[2*j], vv[2*j+1], hp[j], lp[j]);
            part = fmaf(vv[2*j], vv[2*j], fmaf(vv[2*j+1], vv[2*j+1], part));
        }
        int off = (row*LDR + ch*8) * 2;
        *(uint4*)(smem_s + SMEM_QH + off) = make_uint4(hp[0],hp[1],hp[2],hp[3]);
        *(uint4*)(smem_s + SMEM_QL + off) = make_uint4(lp[0],lp[1],lp[2],lp[3]);
        part += __shfl_xor_sync(0xffffffffu, part, 1);
        part += __shfl_xor_sync(0xffffffffu, part, 2);
        part += __shfl_xor_sync(0xffffffffu, part, 4);
        if (ch == 0) qn[row] = part;
    }
    __syncthreads();

    // ---- A (Q) ldmatrix addresses (mapping validated in R8) ----
    uint32_t smem_u = (uint32_t)__cvta_generic_to_shared(smem_s);
    const int arow  = ln & 15;
    const int akoff = (ln >> 4) * 8;
    uint32_t aH = smem_u + SMEM_QH + (arow*LDR + akoff)*2;
    uint32_t aL = smem_u + SMEM_QL + (arow*LDR + akoff)*2;

    float c[2][2][4];
    #pragma unroll
    for (int mi = 0; mi < 2; mi++)
        #pragma unroll
        for (int nj = 0; nj < 2; nj++)
            #pragma unroll
            for (int j = 0; j < 4; j++) c[mi][nj][j] = 0.f;

    float en0 = 0.f, en1 = 0.f;   // sq-sums of this lane's dims for rows n0 / n1

    // ---- main: per kk, B frags direct-from-global (ping-pong distance 2) ----
    #pragma unroll
    for (int kk = 0; kk < 4; kk++) {
        float2 f0 = buf[kk&1][0], f1 = buf[kk&1][1];
        float2 f2 = buf[kk&1][2], f3 = buf[kk&1][3];
        if (kk < 2) {
            int o = (kk + 2) * 16;
            buf[kk&1][0] = *(const float2*)(pB0 + o);
            buf[kk&1][1] = *(const float2*)(pB0 + o + 8);
            buf[kk&1][2] = *(const float2*)(pB1 + o);
            buf[kk&1][3] = *(const float2*)(pB1 + o + 8);
        }
        uint32_t bh0,bl0,bh1,bl1,bh2,bl2,bh3,bl3;
        split_pair(f0.x, f0.y, bh0, bl0);
        split_pair(f1.x, f1.y, bh1, bl1);
        split_pair(f2.x, f2.y, bh2, bl2);
        split_pair(f3.x, f3.y, bh3, bl3);
        en0 = fmaf(f0.x,f0.x, fmaf(f0.y,f0.y, fmaf(f1.x,f1.x, fmaf(f1.y,f1.y, en0))));
        en1 = fmaf(f2.x,f2.x, fmaf(f2.y,f2.y, fmaf(f3.x,f3.x, fmaf(f3.y,f3.y, en1))));
        const uint32_t ko = kk * 32;
        #pragma unroll
        for (int mi = 0; mi < 2; mi++) {
            uint32_t ah[4], al[4];
            ldsm_x4(ah[0],ah[1],ah[2],ah[3], aH + mi*16*LDR*2 + ko);
            ldsm_x4(al[0],al[1],al[2],al[3], aL + mi*16*LDR*2 + ko);
            // dot = Ah*Bh + Ah*Bl + Al*Bh   (lo*lo dropped, ~2^-16)
            mma_bf16(c[mi][0], ah, bh0, bh1);
            mma_bf16(c[mi][1], ah, bh2, bh3);
            mma_bf16(c[mi][0], ah, bl0, bl1);
            mma_bf16(c[mi][1], ah, bl2, bl3);
            mma_bf16(c[mi][0], al, bh0, bh1);
            mma_bf16(c[mi][1], al, bh2, bh3);
        }
    }

    // ---- entity norms: reduce over the 4-lane k-group, redistribute to col owners ----
    en0 += __shfl_xor_sync(0xffffffffu, en0, 1);
    en0 += __shfl_xor_sync(0xffffffffu, en0, 2);
    en1 += __shfl_xor_sync(0xffffffffu, en1, 1);
    en1 += __shfl_xor_sync(0xffffffffu, en1, 2);
    // c-frag lane owns cols 2t, 2t+1; their norms live in lanes 8t / 8t+4
    float enA0 = __shfl_sync(0xffffffffu, en0, 8*t);
    float enA1 = __shfl_sync(0xffffffffu, en0, 8*t + 4);
    float enB0 = __shfl_sync(0xffffffffu, en1, 8*t);
    float enB1 = __shfl_sync(0xffffffffu, en1, 8*t + 4);

    // ---- epilogue: dist^2 = qn + en - 2*dot ; out = MARGIN - sqrt(max(.,0)) ----
    const int cb = 2 * t;
    #pragma unroll
    for (int mi = 0; mi < 2; mi++) {
        #pragma unroll
        for (int nj = 0; nj < 2; nj++) {
            long long eg = ebase + nbase + nj*8 + cb;
            if (eg < NEI) {   // eg even, NEI even -> pair-safe
                float el = nj ? enB0 : enA0;
                float eh = nj ? enB1 : enA1;
                int row = mi*16 + g;
                float q0 = qn[row], q1 = qn[row + 8];
                float d0 = q0 + el - 2.f * c[mi][nj][0];
                float d1 = q0 + eh - 2.f * c[mi][nj][1];
                float d2 = q1 + el - 2.f * c[mi][nj][2];
                float d3 = q1 + eh - 2.f * c[mi][nj][3];
                float v0 = MARGIN - sqrtf(fmaxf(d0, 0.f));
                float v1 = MARGIN - sqrtf(fmaxf(d1, 0.f));
                float v2 = MARGIN - sqrtf(fmaxf(d2, 0.f));
                float v3 = MARGIN - sqrtf(fmaxf(d3, 0.f));
                *(float2*)(out + (long long)row * NEI + eg)       = make_float2(v0, v1);
                *(float2*)(out + (long long)(row + 8) * NEI + eg) = make_float2(v2, v3);
            }
        }
    }
}

extern "C" void kernel_launch(void* const* d_in, const int* in_sizes, int n_in,
                              void* d_out, int out_size) {
    (void)in_sizes; (void)n_in; (void)out_size;
    const void* sub      = d_in[0];
    const void* rel      = d_in[1];
    const float* emb_e   = (const float*)d_in[2];
    const float* emb_rel = (const float*)d_in[3];
    float* out = (float*)d_out;

    int grid = (NEI + EPB - 1) / EPB;   // 782 blocks
    transe_kernel<<<grid, TPB>>>(sub, rel, emb_e, emb_rel, out);
}